// round 10
// baseline (speedup 1.0000x reference)
#include <cuda_runtime.h>

#define NB 4096
#define NT 512
#define OBS 2
#define LAT 4
#define NH 20
#define RNNH 25

#define NWPB 7
#define NBLK 296

#define OFF_Z0   (NB * NT * OBS)
#define OFF_MEAN (OFF_Z0 + NB * LAT)
#define OFF_LV   (OFF_MEAN + NB * LAT)

__device__ float g_predz[NB * NT * LAT];

typedef unsigned long long u64;

__device__ u64 g_m1d[NH * NH];   // [j*NH+i] = dup2(M1[i][j]), M1 = f3_w @ f1_w
__device__ u64 g_c1d[NH];        // dup2((b3 @ f1_w)[j])
__device__ u64 g_w3d[10 * 8];    // [i*8+el] = dup2(f3_w[(half*10+i)*LAT + l4]), el=half*4+l4

__device__ __forceinline__ u64 pack2(float lo, float hi) {
    u64 r; asm("mov.b64 %0, {%1,%2};" : "=l"(r) : "f"(lo), "f"(hi)); return r;
}
__device__ __forceinline__ u64 dup2(float x) { return pack2(x, x); }
__device__ __forceinline__ void unpack2(u64 p, float& lo, float& hi) {
    asm("mov.b64 {%0,%1}, %2;" : "=f"(lo), "=f"(hi) : "l"(p));
}
__device__ __forceinline__ u64 fma2(u64 a, u64 b, u64 c) {
    u64 d; asm("fma.rn.f32x2 %0, %1, %2, %3;" : "=l"(d) : "l"(a), "l"(b), "l"(c));
    return d;
}
__device__ __forceinline__ u64 add2(u64 a, u64 b) {
    u64 d; asm("add.rn.f32x2 %0, %1, %2;" : "=l"(d) : "l"(a), "l"(b)); return d;
}

__device__ __forceinline__ float elu_f(float x) {
    return fmaxf(x, 0.f) + (__expf(fminf(x, 0.f)) - 1.f);
}
__device__ __forceinline__ u64 elu2(u64 p) {
    float a, b; unpack2(p, a, b);
    return pack2(elu_f(a), elu_f(b));
}
__device__ __forceinline__ float fast_tanh(float x) {
    float e = __expf(2.f * x);                  // inf for big x -> 1; 0 for -inf -> -1
    return 1.f - __fdividef(2.f, e + 1.f);
}

// ---------------------------------------------------------------------------
// Kernel 0: precompute composed matrices (tiny).
// ---------------------------------------------------------------------------
__global__ void prep_kernel(const float* __restrict__ f1_w,
                            const float* __restrict__ f3_w,
                            const float* __restrict__ f3_b)
{
    int idx = threadIdx.x;
    for (int p = idx; p < NH * NH; p += 128) {
        int j = p / NH, i = p % NH;
        float s = 0.f;
#pragma unroll
        for (int l = 0; l < LAT; ++l) s += f3_w[i * LAT + l] * f1_w[l * NH + j];
        g_m1d[j * NH + i] = dup2(s);
    }
    if (idx < NH) {
        float s = 0.f;
#pragma unroll
        for (int l = 0; l < LAT; ++l) s += f3_b[l] * f1_w[l * NH + idx];
        g_c1d[idx] = dup2(s);
    }
    if (idx < 80) {
        int i = idx / 8, el = idx % 8;
        int half = el >> 2, l4 = el & 3;
        g_w3d[idx] = dup2(f3_w[(half * 10 + i) * LAT + l4]);
    }
}

// ---------------------------------------------------------------------------
// Kernel 1: backward RNN scan + encoder head + z0 (round-8 structure,
// cheaper tanh). 7 warps/block, grid 296. One warp = TWO batches.
// ---------------------------------------------------------------------------
__global__ __launch_bounds__(NWPB * 32)
void rnn_kernel(const float* __restrict__ trajs,
                const float* __restrict__ eps,
                const float* __restrict__ i2h_w,
                const float* __restrict__ i2h_b,
                const float* __restrict__ h2o_w,
                const float* __restrict__ h2o_b,
                float* __restrict__ out)
{
    const int wIn  = threadIdx.x >> 5;
    const int lane = threadIdx.x & 31;
    const int gw   = blockIdx.x * NWPB + wIn;
    if (gw >= NB / 2) return;
    const int b0   = 2 * gw;
    const int b1   = b0 + 1;

    __shared__ __align__(16) float2 hs[NWPB][2][28];

    const int j = (lane < RNNH) ? lane : 0;
    u64 wx0 = dup2(i2h_w[j]);
    u64 wx1 = dup2(i2h_w[RNNH + j]);
    u64 wh[28];
#pragma unroll
    for (int i = 0; i < RNNH; ++i) wh[i] = dup2(i2h_w[(2 + i) * RNNH + j]);
#pragma unroll
    for (int i = RNNH; i < 28; ++i) wh[i] = 0ull;
    u64 bb = dup2(i2h_b[j]);

    if (lane < 28) {
        hs[wIn][0][lane] = make_float2(0.f, 0.f);
        hs[wIn][1][lane] = make_float2(0.f, 0.f);
    }
    __syncwarp();

    const float2* xrow0 = (const float2*)trajs + (size_t)b0 * NT;
    const float2* xrow1 = (const float2*)trajs + (size_t)b1 * NT;

    float2 nx0 = xrow0[NT - 1];
    float2 nx1 = xrow1[NT - 1];

    int cur = 0;
    for (int t = NT - 1; t >= 0; --t) {
        float2 x0 = nx0, x1 = nx1;
        if (t > 0) { nx0 = xrow0[t - 1]; nx1 = xrow1[t - 1]; }

        u64 a0 = fma2(pack2(x0.x, x1.x), wx0,
                 fma2(pack2(x0.y, x1.y), wx1, bb));
        u64 a1 = 0ull;
        const ulonglong2* hb = (const ulonglong2*)hs[wIn][cur];
#pragma unroll
        for (int q = 0; q < 14; ++q) {
            ulonglong2 hv = hb[q];
            a0 = fma2(hv.x, wh[2 * q + 0], a0);
            a1 = fma2(hv.y, wh[2 * q + 1], a1);
        }
        u64 acc = add2(a0, a1);
        float alo, ahi; unpack2(acc, alo, ahi);
        if (lane < RNNH)
            hs[wIn][cur ^ 1][lane] = make_float2(fast_tanh(alo), fast_tanh(ahi));
        __syncwarp();
        cur ^= 1;
    }

    u64 o = 0ull;
    if (lane < 8) {
        o = dup2(h2o_b[lane]);
        const float2* hl = hs[wIn][cur];
#pragma unroll
        for (int i = 0; i < RNNH; ++i) {
            float2 h = hl[i];
            o = fma2(pack2(h.x, h.y), dup2(h2o_w[i * 8 + lane]), o);
        }
    }
    u64 lv = __shfl_sync(0xffffffffu, o, lane + 4);
    if (lane < LAT) {
        float m0, m1, l0, l1;
        unpack2(o, m0, m1);
        unpack2(lv, l0, l1);
        float z00 = fmaf(eps[b0 * LAT + lane], expf(0.5f * l0), m0);
        float z01 = fmaf(eps[b1 * LAT + lane], expf(0.5f * l1), m1);
        out[OFF_MEAN + b0 * LAT + lane] = m0;
        out[OFF_MEAN + b1 * LAT + lane] = m1;
        out[OFF_Z0 + b0 * LAT + lane] = z00;
        out[OFF_Z0 + b1 * LAT + lane] = z01;
        g_predz[(size_t)b0 * NT * LAT + lane] = z00;
        g_predz[(size_t)b1 * NT * LAT + lane] = z01;
    }
    if (lane >= 4 && lane < 8) {
        float l0, l1; unpack2(o, l0, l1);
        out[OFF_LV + b0 * LAT + (lane - 4)] = l0;
        out[OFF_LV + b1 * LAT + (lane - 4)] = l1;
    }
}

// ---------------------------------------------------------------------------
// Kernel 2: RK4 ODE scan in y-space (y = z @ f1_w).
// Per eval: u1=elu(yi+b1) | sync | layer2 -> u2, sacc | sync | per-lane
// 20x20 M1 matvec, lane-local yi update. z recovered per STEP by lanes 24-31.
// 2 syncwarps per eval, no shfl broadcast, no z round-trip.
// ---------------------------------------------------------------------------
__global__ __launch_bounds__(NWPB * 32, 2)
void ode_kernel(const float* __restrict__ ts,
                const float* __restrict__ f1_w, const float* __restrict__ f1_b,
                const float* __restrict__ f2_w, const float* __restrict__ f2_b,
                const float* __restrict__ f3_w, const float* __restrict__ f3_b)
{
    const int wIn  = threadIdx.x >> 5;
    const int lane = threadIdx.x & 31;
    const int gw   = blockIdx.x * NWPB + wIn;

    __shared__ __align__(16) u64 sbuf[NWPB][44];   // [0..19]=u1, [22..41]=u2/sacc
    __shared__ float s_dt[NT];
    __shared__ u64 w3s[80];

    for (int i = threadIdx.x; i < NT - 1; i += blockDim.x)
        s_dt[i] = ts[i + 1] - ts[i];
    for (int i = threadIdx.x; i < 80; i += blockDim.x)
        w3s[i] = g_w3d[i];
    __syncthreads();
    if (gw >= NB / 2) return;

    const int b0 = 2 * gw;
    const int b1 = b0 + 1;
    u64* su1 = sbuf[wIn];
    u64* su2 = sbuf[wIn] + 22;

    const int j = (lane < NH) ? lane : 0;
    u64 w2c[NH];
#pragma unroll
    for (int i = 0; i < NH; ++i) w2c[i] = dup2(f2_w[i * NH + j]);
    u64 b2r = dup2(f2_b[j]);
    u64 b1r = dup2(f1_b[j]);
    u64 m1c[NH];
#pragma unroll
    for (int i = 0; i < NH; ++i) m1c[i] = g_m1d[j * NH + i];
    u64 c1r = g_c1d[j];

    // epilogue lanes 24..31: el = lane-24; lanes 24..27 hold z components
    const int l4 = lane & 3;
    u64 b3r = dup2(f3_b[l4]);

    const float* z00 = &g_predz[(size_t)b0 * NT * LAT];
    const float* z01 = &g_predz[(size_t)b1 * NT * LAT];
    u64 zc = 0ull;
    if (lane >= 24 && lane < 28)
        zc = pack2(z00[l4], z01[l4]);

    // y = z0 @ f1_w (lane j owns y_j, both batches packed)
    u64 y = 0ull;
#pragma unroll
    for (int i = 0; i < LAT; ++i)
        y = fma2(pack2(z00[i], z01[i]), dup2(f1_w[i * NH + j]), y);
    u64 yi = y, sacc = 0ull;

    const u64 two = dup2(2.f);

    for (int t = 0; t < NT - 1; ++t) {
        const float dt = s_dt[t];
        const u64 hdt  = dup2(0.5f * dt);
        const u64 fdtm = dup2(dt);
        const u64 sdt6 = dup2(dt * (1.f / 6.f));
#pragma unroll
        for (int e = 0; e < 4; ++e) {
            // Phase A: u1 = elu(yi + b1)
            u64 u1 = elu2(add2(yi, b1r));
            if (lane < NH) su1[lane] = u1;
            __syncwarp();

            // Phase B: u2 = elu(u1 @ W2 + b2); sacc update; store u2 (or sacc on e=3)
            u64 c0 = b2r, c1v = 0ull;
            const ulonglong2* u1v = (const ulonglong2*)su1;
#pragma unroll
            for (int q = 0; q < 10; ++q) {
                ulonglong2 v = u1v[q];
                c0  = fma2(v.x, w2c[2 * q + 0], c0);
                c1v = fma2(v.y, w2c[2 * q + 1], c1v);
            }
            u64 u2 = elu2(add2(c0, c1v));
            if (e == 0)      sacc = u2;
            else if (e == 3) sacc = add2(sacc, u2);
            else             sacc = fma2(two, u2, sacc);
            if (lane < NH) su2[lane] = (e == 3) ? sacc : u2;
            __syncwarp();

            // Phase C: per-lane M1 matvec; lane-local y update. No sync needed.
            if (e < 3) {
                u64 p0 = c1r, p1 = 0ull;
                const ulonglong2* u2v = (const ulonglong2*)su2;
#pragma unroll
                for (int q = 0; q < 10; ++q) {
                    ulonglong2 v = u2v[q];
                    p0 = fma2(v.x, m1c[2 * q + 0], p0);
                    p1 = fma2(v.y, m1c[2 * q + 1], p1);
                }
                u64 dlt = add2(p0, p1);
                yi = fma2((e == 2) ? fdtm : hdt, dlt, y);
            } else {
                // y_{t+1} = y + dt/6*(sacc@M1) + dt*c1
                u64 p0 = 0ull, p1 = 0ull;
                const ulonglong2* u2v = (const ulonglong2*)su2;
#pragma unroll
                for (int q = 0; q < 10; ++q) {
                    ulonglong2 v = u2v[q];
                    p0 = fma2(v.x, m1c[2 * q + 0], p0);
                    p1 = fma2(v.y, m1c[2 * q + 1], p1);
                }
                u64 tmp = add2(p0, p1);
                y = fma2(sdt6, tmp, fma2(fdtm, c1r, y));
                yi = y;

                // z epilogue in lanes 24..31 (otherwise idle):
                // z_{t+1} = z + dt/6*(sacc@f3) + dt*b3
                if (lane >= 24) {
                    const int el = lane - 24;
                    const int half = el >> 2;
                    u64 k0 = 0ull, k1 = 0ull;
                    const ulonglong2* sv = (const ulonglong2*)(su2 + half * 10);
#pragma unroll
                    for (int q = 0; q < 5; ++q) {
                        ulonglong2 v = sv[q];
                        k0 = fma2(v.x, w3s[(2 * q + 0) * 8 + el], k0);
                        k1 = fma2(v.y, w3s[(2 * q + 1) * 8 + el], k1);
                    }
                    u64 kk = add2(k0, k1);
                    kk = add2(kk, __shfl_down_sync(0xff000000u, kk, 4));
                    if (lane < 28) {
                        zc = fma2(sdt6, kk, fma2(fdtm, b3r, zc));
                        float lo, hi; unpack2(zc, lo, hi);
                        g_predz[((size_t)b0 * NT + t + 1) * LAT + l4] = lo;
                        g_predz[((size_t)b1 * NT + t + 1) * LAT + l4] = hi;
                    }
                }
            }
        }
    }
}

// ---------------------------------------------------------------------------
// Kernel 3: decoder — fully parallel over (b, t).
// ---------------------------------------------------------------------------
__global__ __launch_bounds__(256)
void dec_kernel(const float* __restrict__ d1_w, const float* __restrict__ d1_b,
                const float* __restrict__ d2_w, const float* __restrict__ d2_b,
                float* __restrict__ out)
{
    __shared__ float sw1[LAT * NH], sb1[NH], sw2[NH * OBS], sb2[OBS];
    if (threadIdx.x < LAT * NH) sw1[threadIdx.x] = d1_w[threadIdx.x];
    if (threadIdx.x < NH)       sb1[threadIdx.x] = d1_b[threadIdx.x];
    if (threadIdx.x < NH * OBS) sw2[threadIdx.x] = d2_w[threadIdx.x];
    if (threadIdx.x < OBS)      sb2[threadIdx.x] = d2_b[threadIdx.x];
    __syncthreads();

    int idx = blockIdx.x * blockDim.x + threadIdx.x;
    float4 z = *(const float4*)&g_predz[(size_t)idx * LAT];

    float acc0 = sb2[0], acc1 = sb2[1];
#pragma unroll
    for (int jj = 0; jj < NH; ++jj) {
        float h = fmaf(z.x, sw1[0 * NH + jj],
                  fmaf(z.y, sw1[1 * NH + jj],
                  fmaf(z.z, sw1[2 * NH + jj],
                  fmaf(z.w, sw1[3 * NH + jj], sb1[jj]))));
        h = fmaxf(h, 0.f);
        acc0 = fmaf(h, sw2[jj * OBS + 0], acc0);
        acc1 = fmaf(h, sw2[jj * OBS + 1], acc1);
    }
    ((float2*)out)[idx] = make_float2(acc0, acc1);
}

// ---------------------------------------------------------------------------
extern "C" void kernel_launch(void* const* d_in, const int* in_sizes, int n_in,
                              void* d_out, int out_size)
{
    const float* samp_trajs = (const float*)d_in[0];
    const float* samp_ts    = (const float*)d_in[1];
    const float* epsilon    = (const float*)d_in[2];
    const float* i2h_w      = (const float*)d_in[3];
    const float* i2h_b      = (const float*)d_in[4];
    const float* h2o_w      = (const float*)d_in[5];
    const float* h2o_b      = (const float*)d_in[6];
    const float* f1_w       = (const float*)d_in[7];
    const float* f1_b       = (const float*)d_in[8];
    const float* f2_w       = (const float*)d_in[9];
    const float* f2_b       = (const float*)d_in[10];
    const float* f3_w       = (const float*)d_in[11];
    const float* f3_b       = (const float*)d_in[12];
    const float* d1_w       = (const float*)d_in[13];
    const float* d1_b       = (const float*)d_in[14];
    const float* d2_w       = (const float*)d_in[15];
    const float* d2_b       = (const float*)d_in[16];
    float* out = (float*)d_out;

    prep_kernel<<<1, 128>>>(f1_w, f3_w, f3_b);
    rnn_kernel<<<NBLK, NWPB * 32>>>(samp_trajs, epsilon, i2h_w, i2h_b, h2o_w, h2o_b, out);
    ode_kernel<<<NBLK, NWPB * 32>>>(samp_ts, f1_w, f1_b, f2_w, f2_b, f3_w, f3_b);
    dec_kernel<<<(NB * NT) / 256, 256>>>(d1_w, d1_b, d2_w, d2_b, out);
}